// round 16
// baseline (speedup 1.0000x reference)
#include <cuda_runtime.h>
#include <cuda_fp16.h>
#include <cstdint>

#define N_TX   500000
#define N_ACC  100000
#define NE     1000000

#define SCAN_BS   1024
#define N_SCAN_BLKS ((N_TX + SCAN_BS - 1) / SCAN_BS)   // 489

#define B2_STR 68    // uint2 units; conflict-free B frag reads

// Prepack+hist fused kernel block roles
#define PP_XACC_BLKS 3125                       // N_ACC*8 float4 / 256
#define PP_B_BLK     PP_XACC_BLKS               // 3125
#define PP_HIST0     (PP_B_BLK + 1)             // 3126
#define PP_HIST_BLKS ((NE + 255) / 256)         // 3907
#define PP_GRID      (PP_HIST0 + PP_HIST_BLKS)  // 7033

// CSR + prepack scratch
__device__ int g_deg[N_TX];                      // zero-init at load;
__device__ int g_off[N_TX];                      // self-zeroed by compute tail
__device__ int g_sorted_src[NE];
__device__ int g_alloc_ctr;
__device__ __align__(16) uint32_t g_xacc_h[N_ACC * 16];   // x_acc f16x2, 6.4 MB
__device__ __align__(16) uint2    g_Bpre2[24 * B2_STR];   // B pairs {bh0,bh1}

// pack two f32 -> f16x2 (v0 -> low half = even k)
__device__ __forceinline__ uint32_t pack_h2(float v0, float v1) {
    __half2 h = __floats2half2_rn(v0, v1);
    return *(uint32_t*)&h;
}

// ---------------------------------------------------------------------------
// K1 (fused): x_acc -> fp16 | B = W^T f16x2 pairs | degree histogram.
// ---------------------------------------------------------------------------
__global__ void prepack_hist_kernel(const float* __restrict__ x_acc,
                                    const float* __restrict__ Wl,
                                    const float* __restrict__ Wr,
                                    const int*   __restrict__ dst_idx) {
    const int bid = blockIdx.x;
    if (bid < PP_XACC_BLKS) {
        int i = bid * 256 + threadIdx.x;          // over N_ACC*8 = 800000 float4
        if (i < N_ACC * 8) {
            float4 v = ((const float4*)x_acc)[i];
            uint2 pk;
            pk.x = pack_h2(v.x, v.y);
            pk.y = pack_h2(v.z, v.w);
            ((uint2*)g_xacc_h)[i] = pk;
        }
    } else if (bid == PP_B_BLK) {
        // B pairs: entry (kt,t,n) = { f16x2(W[16kt+2t], W[16kt+2t+1]),
        //                             f16x2(W[16kt+2t+8], W[16kt+2t+9]) }
        int n = threadIdx.x & 63;
        int t = threadIdx.x >> 6;     // 0..3
        for (int kt = 0; kt < 6; kt++) {
            int k0 = kt * 16 + 2 * t;
            float wa0 = (k0     < 64) ? Wr[(k0    ) * 64 + n] : Wl[(k0     - 64) * 64 + n];
            float wa1 = (k0 + 1 < 64) ? Wr[(k0 + 1) * 64 + n] : Wl[(k0 + 1 - 64) * 64 + n];
            int k1 = k0 + 8;
            float wb0 = (k1     < 64) ? Wr[(k1    ) * 64 + n] : Wl[(k1     - 64) * 64 + n];
            float wb1 = (k1 + 1 < 64) ? Wr[(k1 + 1) * 64 + n] : Wl[(k1 + 1 - 64) * 64 + n];
            uint2 pr;
            pr.x = pack_h2(wa0, wa1);
            pr.y = pack_h2(wb0, wb1);
            g_Bpre2[(kt * 4 + t) * B2_STR + n] = pr;
        }
    } else {
        int e = (bid - PP_HIST0) * 256 + threadIdx.x;
        if (e < NE) atomicAdd(&g_deg[dst_idx[e]], 1);
    }
}

// Fused scan: block-scan + one global atomic per 1024-row block -> absolute g_off
__global__ void alloc_kernel() {
    __shared__ int sh[SCAN_BS];
    __shared__ int base_s;
    int t = threadIdx.x;
    int idx = blockIdx.x * SCAN_BS + t;
    int v = (idx < N_TX) ? g_deg[idx] : 0;
    sh[t] = v;
    __syncthreads();
    #pragma unroll
    for (int o = 1; o < SCAN_BS; o <<= 1) {
        int add = (t >= o) ? sh[t - o] : 0;
        __syncthreads();
        sh[t] += add;
        __syncthreads();
    }
    if (t == SCAN_BS - 1) base_s = atomicAdd(&g_alloc_ctr, sh[t]);
    __syncthreads();
    if (idx < N_TX) g_off[idx] = base_s + sh[t] - v;   // exclusive start
}

__global__ void place_kernel(const int* __restrict__ src_idx,
                             const int* __restrict__ dst_idx) {
    int e = blockIdx.x * blockDim.x + threadIdx.x;
    if (e >= NE) return;
    int pos = atomicAdd(&g_off[dst_idx[e]], 1);
    g_sorted_src[pos] = src_idx[e];
}

// ---------------------------------------------------------------------------
// Fused compute kernel: interleaved quad-cooperative gather (1 wavefront/edge,
// 4 independent chains per quad = 32 rows in flight per warp) +
// [x|agg][128x96] @ W^T[96x64] single-product f16 m16n8k16; relu + logit.
// 128 threads, 4 warps, warp = 32 rows. ~40 KB smem -> 5 CTA/SM.
// ---------------------------------------------------------------------------
#define RBLK   128
#define A_STR  52    // u32/row; 52%32==20 -> frag bank=(20g+t): bijective
#define H_STR  68    // restage stride (floats)

// dynamic smem (u32 units): Ah | B2
#define SM_AH  0
#define SM_B2  (RBLK * A_STR)                 // 6656 (uint2 base, aligned)
#define SM_TOT (SM_B2 + 24 * B2_STR * 2)      // 9920 u32
#define SMEM_BYTES (SM_TOT * 4)               // 39680 B

__device__ __forceinline__ void mma16(float* c, const uint32_t* a, const uint32_t* b) {
    asm volatile(
        "mma.sync.aligned.m16n8k16.row.col.f32.f16.f16.f32 "
        "{%0,%1,%2,%3}, {%4,%5,%6,%7}, {%8,%9}, {%0,%1,%2,%3};"
        : "+f"(c[0]), "+f"(c[1]), "+f"(c[2]), "+f"(c[3])
        : "r"(a[0]), "r"(a[1]), "r"(a[2]), "r"(a[3]), "r"(b[0]), "r"(b[1]));
}

__global__ void __launch_bounds__(128, 5)
compute_kernel(const float* __restrict__ x_tx,
               const float* __restrict__ bl,   // [64]
               const float* __restrict__ Wout, // [64]
               const float* __restrict__ bout, // [1]
               float* __restrict__ out) {
    extern __shared__ uint32_t smem_u32[];
    uint32_t* Ah = smem_u32 + SM_AH;
    uint2*    B2 = (uint2*)(smem_u32 + SM_B2);
    float* restage = (float*)smem_u32;   // overlays everything after GEMM
    __shared__ float bl_s[64];
    __shared__ float wout_s[64];

    const int tid  = threadIdx.x;
    const int wid  = tid >> 5;
    const int lane = tid & 31;
    const int r0   = blockIdx.x * RBLK;

    if (tid < 64) { bl_s[tid] = bl[tid]; wout_s[tid] = Wout[tid]; }

    // ---- Stage A (x_tx part), coalesced: warp covers 512 contiguous bytes ----
    {
        #pragma unroll
        for (int it = 0; it < 16; it++) {
            int idx = tid + it * 128;        // 0..2047
            int row = idx >> 4, j = idx & 15;
            int r = r0 + row;
            float4 v = make_float4(0.f, 0.f, 0.f, 0.f);
            if (r < N_TX) v = __ldcs((const float4*)x_tx + (size_t)r * 16 + j);
            uint2 pk;
            pk.x = pack_h2(v.x, v.y);
            pk.y = pack_h2(v.z, v.w);
            *(uint2*)(Ah + row * A_STR + j * 2) = pk;
        }
    }

    // ---- Stage B: contiguous uint4 copy of prepacked pairs ----
    {
        const uint4* src = (const uint4*)g_Bpre2;
        uint4* dst = (uint4*)B2;
        #pragma unroll
        for (int i = tid; i < (24 * B2_STR) / 2; i += 128) dst[i] = src[i];
    }

    // ---- Interleaved quad gather: quad owns rows {rbw+q, +8, +16, +24};
    //      single loop over max degree with 4 independent chains in flight.
    //      Lane tq loads 16B of the 64B fp16 row -> ~1 wavefront per edge. ----
    {
        const int q   = lane >> 2;     // quad 0..7
        const int tq  = lane & 3;
        const int rbw = wid * 32;

        float a[4][8];
        int cnt[4], start[4];
        int mx = 0;
        #pragma unroll
        for (int p = 0; p < 4; p++) {
            #pragma unroll
            for (int d = 0; d < 8; d++) a[p][d] = 0.f;
            const int r = r0 + rbw + p * 8 + q;
            cnt[p] = 0; start[p] = 0;
            if (r < N_TX) {
                cnt[p] = g_deg[r];
                start[p] = g_off[r] - cnt[p];
            }
            mx = max(mx, cnt[p]);
        }

        for (int i = 0; i < mx; i++) {
            #pragma unroll
            for (int p = 0; p < 4; p++) {
                if (i < cnt[p]) {
                    int s = __ldcs(g_sorted_src + start[p] + i);
                    uint4 w = ((const uint4*)(g_xacc_h + (size_t)s * 16))[tq];
                    float2 f;
                    f = __half22float2(*(__half2*)&w.x); a[p][0] += f.x; a[p][1] += f.y;
                    f = __half22float2(*(__half2*)&w.y); a[p][2] += f.x; a[p][3] += f.y;
                    f = __half22float2(*(__half2*)&w.z); a[p][4] += f.x; a[p][5] += f.y;
                    f = __half22float2(*(__half2*)&w.w); a[p][6] += f.x; a[p][7] += f.y;
                }
            }
        }

        #pragma unroll
        for (int p = 0; p < 4; p++) {
            const int row = rbw + p * 8 + q;
            float inv = 1.f / (float)max(cnt[p], 1);
            uint4 pk;
            pk.x = pack_h2(a[p][0] * inv, a[p][1] * inv);
            pk.y = pack_h2(a[p][2] * inv, a[p][3] * inv);
            pk.z = pack_h2(a[p][4] * inv, a[p][5] * inv);
            pk.w = pack_h2(a[p][6] * inv, a[p][7] * inv);
            *(uint4*)(Ah + row * A_STR + 32 + tq * 4) = pk;  // kp 32+4tq..+3
        }
    }
    __syncthreads();

    const int t  = lane & 3;
    const int g  = lane >> 2;
    const int rb = wid * 32;

    // Accumulators [mtile][ntile][4], seeded with bias
    float acc[2][8][4];
    #pragma unroll
    for (int nt = 0; nt < 8; nt++) {
        float b0 = bl_s[nt * 8 + t * 2];
        float b1 = bl_s[nt * 8 + t * 2 + 1];
        #pragma unroll
        for (int mt = 0; mt < 2; mt++) {
            acc[mt][nt][0] = b0; acc[mt][nt][1] = b1;
            acc[mt][nt][2] = b0; acc[mt][nt][3] = b1;
        }
    }

    #pragma unroll
    for (int kt = 0; kt < 6; kt++) {
        const int kp0 = kt * 8;
        uint32_t af[2][4];
        #pragma unroll
        for (int mt = 0; mt < 2; mt++) {
            const uint32_t* Ap = Ah + (rb + mt * 16 + g) * A_STR + kp0 + t;
            af[mt][0] = Ap[0];                 // (row g,   kp t)
            af[mt][1] = Ap[8 * A_STR];         // (row g+8, kp t)
            af[mt][2] = Ap[4];                 // (row g,   kp t+4)
            af[mt][3] = Ap[8 * A_STR + 4];     // (row g+8, kp t+4)
        }
        const uint2* Brow = B2 + (kt * 4 + t) * B2_STR;
        #pragma unroll
        for (int nt = 0; nt < 8; nt++) {
            uint2 bb = Brow[nt * 8 + g];
            uint32_t bh[2] = { bb.x, bb.y };
            mma16(acc[0][nt], af[0], bh);
            mma16(acc[1][nt], af[1], bh);
        }
    }
    __syncthreads();   // done reading A/B; reuse smem as restage buffer

    // ---- Epilogue: relu + logit dot + restage ----
    #pragma unroll
    for (int mt = 0; mt < 2; mt++) {
        #pragma unroll
        for (int half = 0; half < 2; half++) {
            const int row = rb + mt * 16 + half * 8 + g;
            float* hrow = restage + row * H_STR;
            float partial = 0.f;
            #pragma unroll
            for (int nt = 0; nt < 8; nt++) {
                float h0 = fmaxf(acc[mt][nt][half * 2 + 0], 0.f);
                float h1 = fmaxf(acc[mt][nt][half * 2 + 1], 0.f);
                int col = nt * 8 + t * 2;
                partial += h0 * wout_s[col] + h1 * wout_s[col + 1];
                *(float2*)(hrow + col) = make_float2(h0, h1);
            }
            partial += __shfl_xor_sync(0xffffffffu, partial, 1);
            partial += __shfl_xor_sync(0xffffffffu, partial, 2);
            int r = r0 + row;
            if (t == 0 && r < N_TX) __stcs(out + r, partial + bout[0]);
        }
    }
    __syncthreads();

    // ---- Coalesced tx_x store (streaming) ----
    {
        const int vr = (N_TX - r0 < RBLK) ? (N_TX - r0) : RBLK;
        float4* dst = (float4*)(out + N_TX + (size_t)r0 * 64);
        #pragma unroll
        for (int i = tid; i < RBLK * 16; i += 128) {
            int row = i >> 4, c = i & 15;
            if (row < vr)
                __stcs(dst + row * 16 + c,
                       *(float4*)(restage + row * H_STR + c * 4));
        }
    }

    // ---- Self-clean for next replay (stream-ordered; g_deg reads done) ----
    {
        int r = r0 + tid;
        if (r < N_TX) g_deg[r] = 0;
        if (blockIdx.x == 0 && tid == 0) g_alloc_ctr = 0;
    }
}

// ---------------------------------------------------------------------------
extern "C" void kernel_launch(void* const* d_in, const int* in_sizes, int n_in,
                              void* d_out, int out_size) {
    const float* x_tx     = (const float*)d_in[0];
    const float* x_acc    = (const float*)d_in[1];
    const int*   pays_src = (const int*)d_in[2];
    const int*   pays_dst = (const int*)d_in[3];
    // d_in[4], d_in[5]: rev edges — dead code in reference (h_acc unused)
    const float* Wl_pays  = (const float*)d_in[6];
    const float* bl_pays  = (const float*)d_in[7];
    const float* Wr_pays  = (const float*)d_in[8];
    // d_in[9..11]: rev weights — unused
    const float* W_out    = (const float*)d_in[12];
    const float* b_out    = (const float*)d_in[13];
    float* out = (float*)d_out;   // [logits(500000) | tx_x(500000*64)]

    cudaFuncSetAttribute(compute_kernel,
                         cudaFuncAttributeMaxDynamicSharedMemorySize, SMEM_BYTES);

    prepack_hist_kernel<<<PP_GRID, 256>>>(x_acc, Wl_pays, Wr_pays, pays_dst);
    alloc_kernel<<<N_SCAN_BLKS, SCAN_BS>>>();
    place_kernel<<<(NE + 255) / 256, 256>>>(pays_src, pays_dst);
    compute_kernel<<<(N_TX + RBLK - 1) / RBLK, RBLK, SMEM_BYTES>>>(
        x_tx, bl_pays, W_out, b_out, out);
}

// round 17
// speedup vs baseline: 1.2099x; 1.2099x over previous
#include <cuda_runtime.h>
#include <cuda_fp16.h>
#include <cstdint>

#define N_TX   500000
#define N_ACC  100000
#define NE     1000000

#define SCAN_BS   1024
#define N_SCAN_BLKS ((N_TX + SCAN_BS - 1) / SCAN_BS)   // 489

#define B2_STR 68    // uint2 units; per-phase bank 8t+2g -> conflict-free

// Prepack+hist fused kernel block roles
#define PP_XACC_BLKS 3125                       // N_ACC*8 float4 / 256
#define PP_B_BLK     PP_XACC_BLKS               // 3125
#define PP_HIST0     (PP_B_BLK + 1)             // 3126
#define PP_HIST_BLKS ((NE + 255) / 256)         // 3907
#define PP_GRID      (PP_HIST0 + PP_HIST_BLKS)  // 7033

// CSR + prepack scratch
__device__ int g_deg[N_TX];                      // zero-init at load;
__device__ int g_off[N_TX];                      // self-zeroed by compute tail
__device__ int g_sorted_src[NE];
__device__ int g_alloc_ctr;
__device__ __align__(16) uint32_t g_xacc_h[N_ACC * 16];   // x_acc f16x2, 6.4 MB
__device__ __align__(16) uint2    g_Bpre2[24 * B2_STR];   // B pairs {bh0,bh1}

// pack two f32 -> f16x2 (v0 -> low half = even k)
__device__ __forceinline__ uint32_t pack_h2(float v0, float v1) {
    __half2 h = __floats2half2_rn(v0, v1);
    return *(uint32_t*)&h;
}

// ---------------------------------------------------------------------------
// K1 (fused): x_acc -> fp16 | B = W^T f16x2 pairs | degree histogram.
// ---------------------------------------------------------------------------
__global__ void prepack_hist_kernel(const float* __restrict__ x_acc,
                                    const float* __restrict__ Wl,
                                    const float* __restrict__ Wr,
                                    const int*   __restrict__ dst_idx) {
    const int bid = blockIdx.x;
    if (bid < PP_XACC_BLKS) {
        int i = bid * 256 + threadIdx.x;          // over N_ACC*8 = 800000 float4
        if (i < N_ACC * 8) {
            float4 v = ((const float4*)x_acc)[i];
            uint2 pk;
            pk.x = pack_h2(v.x, v.y);
            pk.y = pack_h2(v.z, v.w);
            ((uint2*)g_xacc_h)[i] = pk;
        }
    } else if (bid == PP_B_BLK) {
        // B pairs: entry (kt,t,n) = { f16x2(W[16kt+2t], W[16kt+2t+1]),
        //                             f16x2(W[16kt+2t+8], W[16kt+2t+9]) }
        int n = threadIdx.x & 63;
        int t = threadIdx.x >> 6;     // 0..3
        for (int kt = 0; kt < 6; kt++) {
            int k0 = kt * 16 + 2 * t;
            float wa0 = (k0     < 64) ? Wr[(k0    ) * 64 + n] : Wl[(k0     - 64) * 64 + n];
            float wa1 = (k0 + 1 < 64) ? Wr[(k0 + 1) * 64 + n] : Wl[(k0 + 1 - 64) * 64 + n];
            int k1 = k0 + 8;
            float wb0 = (k1     < 64) ? Wr[(k1    ) * 64 + n] : Wl[(k1     - 64) * 64 + n];
            float wb1 = (k1 + 1 < 64) ? Wr[(k1 + 1) * 64 + n] : Wl[(k1 + 1 - 64) * 64 + n];
            uint2 pr;
            pr.x = pack_h2(wa0, wa1);
            pr.y = pack_h2(wb0, wb1);
            g_Bpre2[(kt * 4 + t) * B2_STR + n] = pr;
        }
    } else {
        int e = (bid - PP_HIST0) * 256 + threadIdx.x;
        if (e < NE) atomicAdd(&g_deg[dst_idx[e]], 1);
    }
}

// ---------------------------------------------------------------------------
// Fused scan (warp-shuffle): block scan + one global atomic -> absolute g_off
// ---------------------------------------------------------------------------
__global__ void alloc_kernel() {
    __shared__ int wsum[32];
    __shared__ int base_s;
    const int t    = threadIdx.x;
    const int lane = t & 31;
    const int w    = t >> 5;
    const int idx  = blockIdx.x * SCAN_BS + t;
    int v = (idx < N_TX) ? g_deg[idx] : 0;

    // warp inclusive scan
    int x = v;
    #pragma unroll
    for (int o = 1; o < 32; o <<= 1) {
        int y = __shfl_up_sync(0xffffffffu, x, o);
        if (lane >= o) x += y;
    }
    if (lane == 31) wsum[w] = x;
    __syncthreads();

    if (w == 0) {
        int s = (lane < 32) ? wsum[lane] : 0;
        #pragma unroll
        for (int o = 1; o < 32; o <<= 1) {
            int y = __shfl_up_sync(0xffffffffu, s, o);
            if (lane >= o) s += y;
        }
        wsum[lane] = s;                          // inclusive warp-sums scan
        if (lane == 31) base_s = atomicAdd(&g_alloc_ctr, s);
    }
    __syncthreads();

    int wbase = (w > 0) ? wsum[w - 1] : 0;
    if (idx < N_TX) g_off[idx] = base_s + wbase + x - v;   // exclusive start
}

// place: 2 edges per thread (int2 loads) for load-level parallelism
__global__ void place_kernel(const int* __restrict__ src_idx,
                             const int* __restrict__ dst_idx) {
    int i = blockIdx.x * blockDim.x + threadIdx.x;
    if (i >= NE / 2) return;
    int2 d2 = ((const int2*)dst_idx)[i];
    int2 s2 = ((const int2*)src_idx)[i];
    int p0 = atomicAdd(&g_off[d2.x], 1);
    int p1 = atomicAdd(&g_off[d2.y], 1);
    g_sorted_src[p0] = s2.x;
    g_sorted_src[p1] = s2.y;
}

// ---------------------------------------------------------------------------
// Fused compute kernel (R14 structure verbatim; B pair-packed):
// CSR gather-mean (fp16 source, idx-prefetch pipelined, thread = row) +
// [x|agg][128x96] @ W^T[96x64] single-product f16 m16n8k16; relu + logit.
// 128 threads, 4 warps, warp = 32 rows. ~40 KB smem -> 5 CTA/SM.
// ---------------------------------------------------------------------------
#define RBLK   128
#define A_STR  52    // u32/row; 52%32==20 -> frag bank=(20g+t): bijective
#define H_STR  68    // restage stride (floats)

// dynamic smem (u32 units): Ah | B2
#define SM_AH  0
#define SM_B2  (RBLK * A_STR)                 // 6656 (uint2 base, 8B aligned)
#define SM_TOT (SM_B2 + 24 * B2_STR * 2)      // 9920 u32
#define SMEM_BYTES (SM_TOT * 4)               // 39680 B

__device__ __forceinline__ void mma16(float* c, const uint32_t* a, const uint32_t* b) {
    asm volatile(
        "mma.sync.aligned.m16n8k16.row.col.f32.f16.f16.f32 "
        "{%0,%1,%2,%3}, {%4,%5,%6,%7}, {%8,%9}, {%0,%1,%2,%3};"
        : "+f"(c[0]), "+f"(c[1]), "+f"(c[2]), "+f"(c[3])
        : "r"(a[0]), "r"(a[1]), "r"(a[2]), "r"(a[3]), "r"(b[0]), "r"(b[1]));
}

__global__ void __launch_bounds__(128, 5)
compute_kernel(const float* __restrict__ x_tx,
               const float* __restrict__ bl,   // [64]
               const float* __restrict__ Wout, // [64]
               const float* __restrict__ bout, // [1]
               float* __restrict__ out) {
    extern __shared__ uint32_t smem_u32[];
    uint32_t* Ah = smem_u32 + SM_AH;
    uint2*    B2 = (uint2*)(smem_u32 + SM_B2);
    float* restage = (float*)smem_u32;   // overlays everything after GEMM
    __shared__ float bl_s[64];
    __shared__ float wout_s[64];

    const int tid  = threadIdx.x;
    const int wid  = tid >> 5;
    const int lane = tid & 31;
    const int r0   = blockIdx.x * RBLK;

    if (tid < 64) { bl_s[tid] = bl[tid]; wout_s[tid] = Wout[tid]; }

    // ---- Stage A (x_tx part), coalesced: warp covers 512 contiguous bytes ----
    {
        #pragma unroll
        for (int it = 0; it < 16; it++) {
            int idx = tid + it * 128;        // 0..2047
            int row = idx >> 4, j = idx & 15;
            int r = r0 + row;
            float4 v = make_float4(0.f, 0.f, 0.f, 0.f);
            if (r < N_TX) v = __ldcs((const float4*)x_tx + (size_t)r * 16 + j);
            uint2 pk;
            pk.x = pack_h2(v.x, v.y);
            pk.y = pack_h2(v.z, v.w);
            *(uint2*)(Ah + row * A_STR + j * 2) = pk;
        }
    }

    // ---- Stage B: contiguous uint4 copy of prepacked pairs ----
    {
        const uint4* src = (const uint4*)g_Bpre2;
        uint4* dst = (uint4*)B2;
        #pragma unroll
        for (int i = tid; i < (24 * B2_STR) / 2; i += 128) dst[i] = src[i];
    }

    // ---- CSR gather-mean from fp16 x_acc, thread = row, idx prefetch ----
    {
        const int r = r0 + tid;
        uint32_t* AR = Ah + tid * A_STR;
        float a[32];
        #pragma unroll
        for (int d = 0; d < 32; d++) a[d] = 0.f;
        int cnt = 0;
        if (r < N_TX) {
            cnt = g_deg[r];
            int end = g_off[r];           // END pointer after place
            int start = end - cnt;
            if (cnt > 0) {
                int s = __ldcs(g_sorted_src + start);
                for (int i = 0; i < cnt; i++) {
                    int s_next = (i + 1 < cnt) ? __ldcs(g_sorted_src + start + i + 1) : 0;
                    const uint4* p = (const uint4*)(g_xacc_h + (size_t)s * 16);
                    #pragma unroll
                    for (int jj = 0; jj < 4; jj++) {
                        uint4 w = p[jj];
                        float2 f;
                        f = __half22float2(*(__half2*)&w.x);
                        a[jj * 8 + 0] += f.x; a[jj * 8 + 1] += f.y;
                        f = __half22float2(*(__half2*)&w.y);
                        a[jj * 8 + 2] += f.x; a[jj * 8 + 3] += f.y;
                        f = __half22float2(*(__half2*)&w.z);
                        a[jj * 8 + 4] += f.x; a[jj * 8 + 5] += f.y;
                        f = __half22float2(*(__half2*)&w.w);
                        a[jj * 8 + 6] += f.x; a[jj * 8 + 7] += f.y;
                    }
                    s = s_next;
                }
            }
        }
        float inv = 1.f / (float)max(cnt, 1);
        #pragma unroll
        for (int j = 0; j < 16; j++)
            AR[32 + j] = pack_h2(a[j * 2] * inv, a[j * 2 + 1] * inv);
    }
    __syncthreads();

    const int t  = lane & 3;
    const int g  = lane >> 2;
    const int rb = wid * 32;

    // Accumulators [mtile][ntile][4], seeded with bias
    float acc[2][8][4];
    #pragma unroll
    for (int nt = 0; nt < 8; nt++) {
        float b0 = bl_s[nt * 8 + t * 2];
        float b1 = bl_s[nt * 8 + t * 2 + 1];
        #pragma unroll
        for (int mt = 0; mt < 2; mt++) {
            acc[mt][nt][0] = b0; acc[mt][nt][1] = b1;
            acc[mt][nt][2] = b0; acc[mt][nt][3] = b1;
        }
    }

    #pragma unroll
    for (int kt = 0; kt < 6; kt++) {
        const int kp0 = kt * 8;
        uint32_t af[2][4];
        #pragma unroll
        for (int mt = 0; mt < 2; mt++) {
            const uint32_t* Ap = Ah + (rb + mt * 16 + g) * A_STR + kp0 + t;
            af[mt][0] = Ap[0];                 // (row g,   kp t)
            af[mt][1] = Ap[8 * A_STR];         // (row g+8, kp t)
            af[mt][2] = Ap[4];                 // (row g,   kp t+4)
            af[mt][3] = Ap[8 * A_STR + 4];     // (row g+8, kp t+4)
        }
        const uint2* Brow = B2 + (kt * 4 + t) * B2_STR;
        #pragma unroll
        for (int nt = 0; nt < 8; nt++) {
            uint2 bb = Brow[nt * 8 + g];
            uint32_t bh[2] = { bb.x, bb.y };
            mma16(acc[0][nt], af[0], bh);
            mma16(acc[1][nt], af[1], bh);
        }
    }
    __syncthreads();   // done reading A/B; reuse smem as restage buffer

    // ---- Epilogue: relu + logit dot + restage ----
    #pragma unroll
    for (int mt = 0; mt < 2; mt++) {
        #pragma unroll
        for (int half = 0; half < 2; half++) {
            const int row = rb + mt * 16 + half * 8 + g;
            float* hrow = restage + row * H_STR;
            float partial = 0.f;
            #pragma unroll
            for (int nt = 0; nt < 8; nt++) {
                float h0 = fmaxf(acc[mt][nt][half * 2 + 0], 0.f);
                float h1 = fmaxf(acc[mt][nt][half * 2 + 1], 0.f);
                int col = nt * 8 + t * 2;
                partial += h0 * wout_s[col] + h1 * wout_s[col + 1];
                *(float2*)(hrow + col) = make_float2(h0, h1);
            }
            partial += __shfl_xor_sync(0xffffffffu, partial, 1);
            partial += __shfl_xor_sync(0xffffffffu, partial, 2);
            int r = r0 + row;
            if (t == 0 && r < N_TX) __stcs(out + r, partial + bout[0]);
        }
    }
    __syncthreads();

    // ---- Coalesced tx_x store (streaming) ----
    {
        const int vr = (N_TX - r0 < RBLK) ? (N_TX - r0) : RBLK;
        float4* dst = (float4*)(out + N_TX + (size_t)r0 * 64);
        #pragma unroll
        for (int i = tid; i < RBLK * 16; i += 128) {
            int row = i >> 4, c = i & 15;
            if (row < vr)
                __stcs(dst + row * 16 + c,
                       *(float4*)(restage + row * H_STR + c * 4));
        }
    }

    // ---- Self-clean for next replay (stream-ordered; g_deg reads done) ----
    {
        int r = r0 + tid;
        if (r < N_TX) g_deg[r] = 0;
        if (blockIdx.x == 0 && tid == 0) g_alloc_ctr = 0;
    }
}

// ---------------------------------------------------------------------------
extern "C" void kernel_launch(void* const* d_in, const int* in_sizes, int n_in,
                              void* d_out, int out_size) {
    const float* x_tx     = (const float*)d_in[0];
    const float* x_acc    = (const float*)d_in[1];
    const int*   pays_src = (const int*)d_in[2];
    const int*   pays_dst = (const int*)d_in[3];
    // d_in[4], d_in[5]: rev edges — dead code in reference (h_acc unused)
    const float* Wl_pays  = (const float*)d_in[6];
    const float* bl_pays  = (const float*)d_in[7];
    const float* Wr_pays  = (const float*)d_in[8];
    // d_in[9..11]: rev weights — unused
    const float* W_out    = (const float*)d_in[12];
    const float* b_out    = (const float*)d_in[13];
    float* out = (float*)d_out;   // [logits(500000) | tx_x(500000*64)]

    cudaFuncSetAttribute(compute_kernel,
                         cudaFuncAttributeMaxDynamicSharedMemorySize, SMEM_BYTES);

    prepack_hist_kernel<<<PP_GRID, 256>>>(x_acc, Wl_pays, Wr_pays, pays_dst);
    alloc_kernel<<<N_SCAN_BLKS, SCAN_BS>>>();
    place_kernel<<<(NE / 2 + 255) / 256, 256>>>(pays_src, pays_dst);
    compute_kernel<<<(N_TX + RBLK - 1) / RBLK, RBLK, SMEM_BYTES>>>(
        x_tx, bl_pays, W_out, b_out, out);
}